// round 16
// baseline (speedup 1.0000x reference)
#include <cuda_runtime.h>
#include <cstdint>

#define NN 4096      // nodes
#define NE 4096      // hyperedges
#define NF 128       // features
#define CAP 192      // per-list capacity (max degree ~58 expected)

#define THETA_CTAS 144          // 128 theta tiles + 16 inverse CTAs (run first)
#define BUILD_CTAS 1024
#define PAIR_MAX   1024         // staging capacity (avg ~128 nz per 4-row CTA)
#define NSTAGES    8            // 8 stages x 8 KB = 64 KB (4 H rows) per CTA
#define PIPE       4            // stage ring depth

// ---------------- scratch (static __device__, zero-initialized) ----------
__device__ float g_theta[NN * NF];        // X @ W            (2 MB, L2-resident)
__device__ float g_U[NE * NF];            // De^-1 H^T theta  (2 MB)
__device__ float g_inv_dv[NN];
__device__ float g_inv_de[NE];
__device__ int   g_col_cnt[NE];           // MUST be 0 at k_fused entry (zero at load;
__device__ int   g_row_cnt[NN];           //  spmm1/spmm2 re-zero after reading)
__device__ int   g_col_idx[NE * CAP];
__device__ int   g_row_idx[NN * CAP];

// ---------------- cp.async helpers ---------------------------------------
__device__ __forceinline__ void cp_async16(uint32_t saddr, const void* gaddr) {
    asm volatile("cp.async.cg.shared.global [%0], [%1], 16;\n"
                 :: "r"(saddr), "l"(gaddr) : "memory");
}
__device__ __forceinline__ void cp_commit() {
    asm volatile("cp.async.commit_group;\n" ::: "memory");
}
template <int N>
__device__ __forceinline__ void cp_wait() {
    asm volatile("cp.async.wait_group %0;\n" :: "n"(N) : "memory");
}

// ---------------- K1: fused theta + init + CSR/CSC build -----------------
// blockIdx roles:  [0, 128)        -> theta tile
//                  [128, 144)      -> diag inverses
//                  [144, 144+1024) -> build: 4 H rows, cp.async pipelined scan
__global__ void __launch_bounds__(256) k_fused(const float* __restrict__ X,
                                               const float* __restrict__ W,
                                               const float* __restrict__ H,
                                               const float* __restrict__ Dv,
                                               const float* __restrict__ De) {
    __shared__ __align__(16) char s_mem[PIPE * 8192];  // stage ring (32 KB) | Xs
    __shared__ unsigned s_pairs[PAIR_MAX];             // 4 KB staging
    __shared__ int s_cnt;

    const int b   = blockIdx.x;
    const int tid = threadIdx.x;

    if (b >= THETA_CTAS) {
        // ---- build: continuous cp.async stream, barrier-free stage loop ---
        // Thread t copies & consumes smem words {t, t+256} of every stage:
        // self-ownership => cp.async.wait_group is a sufficient fence, and
        // buffer-slot reuse (distance PIPE=4 stages) is ordered per-thread.
        const int b2 = b - THETA_CTAS;
        const char* __restrict__ hbase =
            reinterpret_cast<const char*>(H) + (size_t)b2 * 65536;
        int4* bufs = reinterpret_cast<int4*>(s_mem);

        if (tid == 0) s_cnt = 0;
        __syncthreads();                        // s_cnt visible before appends

        // prologue: stages 0..2 in flight
        #pragma unroll
        for (int s = 0; s < 3; s++) {
            uint32_t sb = (uint32_t)__cvta_generic_to_shared(bufs + (s & 3) * 512);
            cp_async16(sb + (uint32_t)tid * 16,
                       hbase + (size_t)(s * 512 + tid) * 16);
            cp_async16(sb + (uint32_t)(tid + 256) * 16,
                       hbase + (size_t)(s * 512 + tid + 256) * 16);
            cp_commit();
        }

        #pragma unroll
        for (int s = 0; s < NSTAGES; s++) {
            if (s + 3 < NSTAGES) {              // keep 3 stages in flight
                int sn = s + 3;
                uint32_t sb = (uint32_t)__cvta_generic_to_shared(bufs + (sn & 3) * 512);
                cp_async16(sb + (uint32_t)tid * 16,
                           hbase + (size_t)(sn * 512 + tid) * 16);
                cp_async16(sb + (uint32_t)(tid + 256) * 16,
                           hbase + (size_t)(sn * 512 + tid + 256) * 16);
            }
            cp_commit();                        // (empty group at tail is legal)
            cp_wait<3>();                       // stage s landed for this thread

            const int4* buf = bufs + (s & 3) * 512;
            #pragma unroll
            for (int k = 0; k < 2; k++) {
                int li = tid + k * 256;         // float4 index within stage
                int4 v = buf[li];               // conflict-free LDS.128
                if ((v.x | v.y | v.z | v.w) != 0) {         // ~3% taken
                    int lf = s * 512 + li;      // float4 idx within CTA (0..4095)
                    unsigned local = (unsigned)(lf >> 10);  // row 0..3
                    unsigned ebase = (unsigned)((lf & 1023) << 2);
                    int comp[4] = {v.x, v.y, v.z, v.w};
                    #pragma unroll
                    for (int c = 0; c < 4; c++) {
                        if (comp[c] != 0) {
                            int p = atomicAdd(&s_cnt, 1);   // smem (~30 cyc)
                            if (p < PAIR_MAX)
                                s_pairs[p] = (local << 12) | (ebase + c);
                        }
                    }
                }
            }
        }
        __syncthreads();                        // staging complete

        // Phase 2: parallel global appends — one atomic round-trip per pair
        int tot = s_cnt < PAIR_MAX ? s_cnt : PAIR_MAX;
        for (int i = tid; i < tot; i += 256) {
            unsigned pr = s_pairs[i];
            int n = b2 * 4 + (int)(pr >> 12);
            int e = (int)(pr & (NE - 1));
            int p = atomicAdd(&g_row_cnt[n], 1);      // 4096 spread addrs
            if (p < CAP) g_row_idx[(size_t)n * CAP + p] = e;
            int q = atomicAdd(&g_col_cnt[e], 1);      // 4096 spread addrs
            if (q < CAP) g_col_idx[(size_t)e * CAP + q] = n;
        }

    } else if (b < 128) {
        // ---- theta = X @ W : 32-row x 128-col tile --------------------
        float (*Xs)[NF] = reinterpret_cast<float (*)[NF]>(s_mem);
        const int row0 = b * 32;
        #pragma unroll
        for (int i = tid; i < 32 * NF; i += 256)
            Xs[i >> 7][i & 127] = X[(size_t)row0 * NF + i];
        __syncthreads();

        const int fp = tid & 63;          // float2 column
        const int rg = tid >> 6;          // row group 0..3
        const float2* __restrict__ W2 = reinterpret_cast<const float2*>(W);

        float acc[8][2];
        #pragma unroll
        for (int i = 0; i < 8; i++) { acc[i][0] = 0.f; acc[i][1] = 0.f; }

        #pragma unroll 4
        for (int k = 0; k < NF; k++) {
            float2 w = __ldg(&W2[k * 64 + fp]);
            #pragma unroll
            for (int i = 0; i < 8; i++) {
                float x = Xs[rg * 8 + i][k];
                acc[i][0] += x * w.x;
                acc[i][1] += x * w.y;
            }
        }
        #pragma unroll
        for (int i = 0; i < 8; i++) {
            int r = row0 + rg * 8 + i;
            *reinterpret_cast<float2*>(&g_theta[(size_t)r * NF + fp * 2]) =
                make_float2(acc[i][0], acc[i][1]);
        }

    } else {
        // ---- diagonal inverses ----------------------------------------
        int i = (b - 128) * 256 + tid;
        if (i < NN) {
            g_inv_dv[i] = 1.0f / Dv[(size_t)i * (NN + 1)];
            g_inv_de[i] = 1.0f / De[(size_t)i * (NE + 1)];
        }
    }
}

// ---------------- SpMM gather core: 4 warps per row, 1 float per lane ----
__device__ __forceinline__ float gather_part(const int* __restrict__ idx,
                                             int cnt,
                                             const float* __restrict__ src) {
    float acc = 0.0f;
    int i = 0;
    for (; i + 8 <= cnt; i += 8) {
        int id[8];
        #pragma unroll
        for (int j = 0; j < 8; j++) id[j] = idx[i + j];
        float v[8];
        #pragma unroll
        for (int j = 0; j < 8; j++) v[j] = src[(size_t)id[j] * NF];
        #pragma unroll
        for (int j = 0; j < 8; j++) acc += v[j];
    }
    for (; i < cnt; i++) acc += src[(size_t)idx[i] * NF];
    return acc;
}

// ---------------- K2: U[e] = inv_de[e] * sum_{n in col[e]} theta[n] ------
// CTA = 256 threads = 8 warps = 2 edges x 4 feature-parts.
__global__ void __launch_bounds__(256) k_spmm1() {
    __shared__ int s_cnt2[2];
    const int tid  = threadIdx.x;
    const int warp = tid >> 5;
    const int lane = tid & 31;
    const int lr   = warp >> 2;           // local row 0..1
    const int part = warp & 3;            // feature part 0..3
    const int e    = blockIdx.x * 2 + lr;

    if (tid < 2) s_cnt2[tid] = g_col_cnt[blockIdx.x * 2 + tid];
    __syncthreads();
    if (tid < 2) g_col_cnt[blockIdx.x * 2 + tid] = 0;   // safe: all read via smem

    int cnt = s_cnt2[lr];
    if (cnt > CAP) cnt = CAP;

    float acc = gather_part(g_col_idx + (size_t)e * CAP, cnt,
                            g_theta + part * 32 + lane);
    g_U[(size_t)e * NF + part * 32 + lane] = acc * g_inv_de[e];
}

// ---------------- K3: Y[n] = inv_dv[n] * sum_{e in row[n]} U[e] ----------
__global__ void __launch_bounds__(256) k_spmm2(float* __restrict__ out) {
    __shared__ int s_cnt2[2];
    const int tid  = threadIdx.x;
    const int warp = tid >> 5;
    const int lane = tid & 31;
    const int lr   = warp >> 2;
    const int part = warp & 3;
    const int n    = blockIdx.x * 2 + lr;

    if (tid < 2) s_cnt2[tid] = g_row_cnt[blockIdx.x * 2 + tid];
    __syncthreads();
    if (tid < 2) g_row_cnt[blockIdx.x * 2 + tid] = 0;   // safe: all read via smem

    int cnt = s_cnt2[lr];
    if (cnt > CAP) cnt = CAP;

    float acc = gather_part(g_row_idx + (size_t)n * CAP, cnt,
                            g_U + part * 32 + lane);
    out[(size_t)n * NF + part * 32 + lane] = acc * g_inv_dv[n];
}

// ---------------- launch --------------------------------------------------
extern "C" void kernel_launch(void* const* d_in, const int* in_sizes, int n_in,
                              void* d_out, int out_size) {
    const float* X  = (const float*)d_in[0];   // [4096,128]
    const float* H  = (const float*)d_in[1];   // [4096,4096]
    const float* Dv = (const float*)d_in[2];   // [4096,4096] diag
    const float* De = (const float*)d_in[3];   // [4096,4096] diag
    const float* W  = (const float*)d_in[4];   // [128,128]
    float* out = (float*)d_out;                // [4096,128]

    k_fused<<<THETA_CTAS + BUILD_CTAS, 256>>>(X, W, H, Dv, De);
    k_spmm1<<<NE / 2, 256>>>();
    k_spmm2<<<NN / 2, 256>>>(out);
}